// round 2
// baseline (speedup 1.0000x reference)
#include <cuda_runtime.h>
#include <cuda_bf16.h>
#include <math.h>

#define GN 100000
#define GF 128
#define GE 640000

// Scratch (device globals — no allocation allowed)
__device__ float g_xw[(size_t)GN * GF];   // x @ W_conv^T
__device__ float g_deg[GN];               // degree -> dinv (in place)
__device__ float g_WT[GF * GF];           // W_conv transposed (k-major)

// ---------------------------------------------------------------------------
// 1) degree init (self-loop contributes 1 to every node)
__global__ void k_deg_init(int N) {
    int i = blockIdx.x * blockDim.x + threadIdx.x;
    if (i < N) g_deg[i] = 1.0f;
}

// 2) in-degree count over edges
__global__ void k_deg_count(const int* __restrict__ dst, int E) {
    int e = blockIdx.x * blockDim.x + threadIdx.x;
    if (e < E) atomicAdd(&g_deg[dst[e]], 1.0f);
}

// 3) dinv = rsqrt(deg)   (deg >= 1 always due to self loops)
__global__ void k_dinv(int N) {
    int i = blockIdx.x * blockDim.x + threadIdx.x;
    if (i < N) g_deg[i] = rsqrtf(g_deg[i]);
}

// 4) transpose W_conv: g_WT[k*128 + j] = W[j*128 + k]
__global__ void k_transpose(const float* __restrict__ W) {
    int t = blockIdx.x * blockDim.x + threadIdx.x;  // 16384 threads
    int k = t >> 7, j = t & 127;
    if (t < GF * GF) g_WT[k * GF + j] = W[j * GF + k];
}

// ---------------------------------------------------------------------------
// 5) GEMM: xw = x @ W^T.  Tile 64 rows x 128 cols per block, 256 threads,
//    each thread computes 8 rows x 4 cols.  Also writes the self-loop
//    contribution dinv[i]^2 * xw[i] into h (d_out's h region).
__global__ __launch_bounds__(256) void k_gemm(const float* __restrict__ x,
                                              float* __restrict__ h, int N) {
    __shared__ float Xs[64][17];    // padded: conflict-free stores
    __shared__ float WsT[16][128];  // k-major chunk of W^T

    const int tid  = threadIdx.x;
    const int row0 = blockIdx.x * 64;
    const int c    = (tid & 31) * 4;  // output col base (0..124)
    const int r    = (tid >> 5) * 8;  // output row base within tile (warp-uniform)

    float acc[8][4];
#pragma unroll
    for (int i = 0; i < 8; i++)
#pragma unroll
        for (int j = 0; j < 4; j++) acc[i][j] = 0.0f;

    for (int k0 = 0; k0 < GF; k0 += 16) {
        // stage X tile 64x16 (coalesced 64B runs)
        for (int e = tid; e < 64 * 16; e += 256) {
            int rr = e >> 4, kk = e & 15;
            int grow = row0 + rr;
            Xs[rr][kk] = (grow < N) ? x[(size_t)grow * GF + k0 + kk] : 0.0f;
        }
        // stage W^T chunk 16x128 from pre-transposed global (fully coalesced,
        // conflict-free smem store)
        for (int e = tid; e < 16 * 128; e += 256) {
            int kk = e >> 7, j = e & 127;
            WsT[kk][j] = g_WT[(k0 + kk) * GF + j];
        }
        __syncthreads();

#pragma unroll
        for (int k = 0; k < 16; k++) {
            float4 w = *(const float4*)&WsT[k][c];  // LDS.128, conflict-free
#pragma unroll
            for (int i = 0; i < 8; i++) {
                float xv = Xs[r + i][k];            // warp-uniform broadcast
                acc[i][0] = fmaf(xv, w.x, acc[i][0]);
                acc[i][1] = fmaf(xv, w.y, acc[i][1]);
                acc[i][2] = fmaf(xv, w.z, acc[i][2]);
                acc[i][3] = fmaf(xv, w.w, acc[i][3]);
            }
        }
        __syncthreads();
    }

#pragma unroll
    for (int i = 0; i < 8; i++) {
        int grow = row0 + r + i;
        if (grow < N) {
            float di   = g_deg[grow];     // dinv
            float self = di * di;         // self-loop norm
            float4 v = make_float4(acc[i][0], acc[i][1], acc[i][2], acc[i][3]);
            *(float4*)&g_xw[(size_t)grow * GF + c] = v;
            float4 hv = make_float4(v.x * self, v.y * self, v.z * self, v.w * self);
            *(float4*)&h[(size_t)grow * GF + c] = hv;
        }
    }
}

// ---------------------------------------------------------------------------
// 6) edge scatter: h[dst] += xw[src] * dinv[src]*dinv[dst]
//    One warp per edge, each lane handles 4 contiguous floats (float4 gather,
//    4 scalar RED.F32).  xw + h both fit in L2 (102 MB of 126 MB).
__global__ __launch_bounds__(256) void k_edges(const int* __restrict__ src,
                                               const int* __restrict__ dst,
                                               float* __restrict__ h, int E) {
    long long t = (long long)blockIdx.x * blockDim.x + threadIdx.x;
    int e = (int)(t >> 5);
    if (e >= E) return;
    int lane = (int)(t & 31);
    int s = __ldg(src + e);               // warp-uniform -> broadcast
    int d = __ldg(dst + e);
    float norm = __ldg(&g_deg[s]) * __ldg(&g_deg[d]);
    float4 v = *(const float4*)(g_xw + (size_t)s * GF + lane * 4);
    float* hp = h + (size_t)d * GF + lane * 4;
    atomicAdd(hp + 0, v.x * norm);
    atomicAdd(hp + 1, v.y * norm);
    atomicAdd(hp + 2, v.z * norm);
    atomicAdd(hp + 3, v.w * norm);
}

// ---------------------------------------------------------------------------
// 7) epilogue: h = relu(agg + b_conv) in place; out = sigmoid(h . W_lin + b_lin)
//    One warp per node.
__global__ __launch_bounds__(256) void k_final(float* __restrict__ h,
                                               const float* __restrict__ bconv,
                                               const float* __restrict__ wlin,
                                               const float* __restrict__ blin,
                                               float* __restrict__ out, int N) {
    int warp = (blockIdx.x * blockDim.x + threadIdx.x) >> 5;
    int lane = threadIdx.x & 31;
    if (warp >= N) return;
    size_t base = (size_t)warp * GF + lane * 4;
    float4 v = *(float4*)(h + base);
    float4 b = *(const float4*)(bconv + lane * 4);
    v.x = fmaxf(v.x + b.x, 0.0f);
    v.y = fmaxf(v.y + b.y, 0.0f);
    v.z = fmaxf(v.z + b.z, 0.0f);
    v.w = fmaxf(v.w + b.w, 0.0f);
    *(float4*)(h + base) = v;
    float4 w = *(const float4*)(wlin + lane * 4);
    float dot = v.x * w.x + v.y * w.y + v.z * w.z + v.w * w.w;
#pragma unroll
    for (int o = 16; o; o >>= 1) dot += __shfl_xor_sync(0xFFFFFFFFu, dot, o);
    if (lane == 0) {
        float z = dot + blin[0];
        out[warp] = 1.0f / (1.0f + expf(-z));
    }
}

// ---------------------------------------------------------------------------
extern "C" void kernel_launch(void* const* d_in, const int* in_sizes, int n_in,
                              void* d_out, int out_size) {
    const float* x  = (const float*)d_in[0];
    const int*   ei = (const int*)d_in[1];
    const float* Wc = (const float*)d_in[2];
    const float* bc = (const float*)d_in[3];
    const float* Wl = (const float*)d_in[4];
    const float* bl = (const float*)d_in[5];

    int N = in_sizes[0] / GF;
    int E = in_sizes[1] / 2;

    float* out = (float*)d_out;
    float* h   = out + N;          // (out, h) flattened: out first, then h
    const int* src = ei;
    const int* dst = ei + E;

    k_deg_init<<<(N + 255) / 256, 256>>>(N);
    k_deg_count<<<(E + 255) / 256, 256>>>(dst, E);
    k_dinv<<<(N + 255) / 256, 256>>>(N);
    k_transpose<<<(GF * GF + 255) / 256, 256>>>(Wc);
    k_gemm<<<(N + 63) / 64, 256>>>(x, h, N);

    long long tot = (long long)E * 32;
    k_edges<<<(unsigned)((tot + 255) / 256), 256>>>(src, dst, h, E);

    k_final<<<(N + 7) / 8, 256>>>(h, bc, Wl, bl, out, N);
}

// round 4
// speedup vs baseline: 1.5521x; 1.5521x over previous
#include <cuda_runtime.h>
#include <cuda_bf16.h>
#include <math.h>

#define GN 100000
#define GF 128
#define GE 640000

// Scratch (device globals — no allocation allowed)
__device__ float g_xw[(size_t)GN * GF];   // x @ W_conv^T
__device__ float g_deg[GN];               // degree -> dinv (in place)

// ---------------------------------------------------------------------------
__global__ void k_deg_init(int N) {
    int i = blockIdx.x * blockDim.x + threadIdx.x;
    if (i < N) g_deg[i] = 1.0f;
}

__global__ void k_deg_count(const int* __restrict__ dst, int E) {
    int e = blockIdx.x * blockDim.x + threadIdx.x;
    if (e < E) atomicAdd(&g_deg[dst[e]], 1.0f);
}

__global__ void k_dinv(int N) {
    int i = blockIdx.x * blockDim.x + threadIdx.x;
    if (i < N) g_deg[i] = rsqrtf(g_deg[i]);
}

// ---------------------------------------------------------------------------
// tf32 helpers
__device__ __forceinline__ unsigned f2tf32(float f) {
    unsigned u;
    asm("cvt.rna.tf32.f32 %0, %1;" : "=r"(u) : "f"(f));
    return u;
}

__device__ __forceinline__ void mma_tf32(float d[4], const unsigned a[4],
                                         const unsigned b[2], const float c[4]) {
    asm volatile(
        "mma.sync.aligned.m16n8k8.row.col.f32.tf32.tf32.f32 "
        "{%0,%1,%2,%3}, {%4,%5,%6,%7}, {%8,%9}, {%10,%11,%12,%13};\n"
        : "=f"(d[0]), "=f"(d[1]), "=f"(d[2]), "=f"(d[3])
        : "r"(a[0]), "r"(a[1]), "r"(a[2]), "r"(a[3]),
          "r"(b[0]), "r"(b[1]),
          "f"(c[0]), "f"(c[1]), "f"(c[2]), "f"(c[3]));
}

// ---------------------------------------------------------------------------
// GEMM: xw = x @ W^T via tf32 mma.sync.  Block tile 256 rows x 128 cols,
// full K=128 resident in smem (tf32 bits).  8 warps, each 64x64.
// Also writes self-loop contribution dinv[i]^2 * xw[i] into h.
#define XS_STR 132
__global__ __launch_bounds__(256) void k_gemm_tf32(const float* __restrict__ x,
                                                   const float* __restrict__ W,
                                                   float* __restrict__ h, int N) {
    extern __shared__ unsigned smem[];
    unsigned* Xs = smem;                    // [256][132]
    unsigned* Ws = smem + 256 * XS_STR;     // [128][132]

    const int tid  = threadIdx.x;
    const int lane = tid & 31;
    const int wid  = tid >> 5;
    const int wr   = wid >> 1;   // warp row group 0..3  (64 rows each)
    const int wc   = wid & 1;    // warp col group 0..1  (64 cols each)
    const int row0 = blockIdx.x * 256;

    // Stage X tile (256x128) as tf32
    for (int e = tid; e < 256 * 128; e += 256) {
        int r = e >> 7, c = e & 127;
        int grow = row0 + r;
        float v = (grow < N) ? x[(size_t)grow * GF + c] : 0.0f;
        Xs[r * XS_STR + c] = f2tf32(v);
    }
    // Stage W (128x128, row = out feature j, col = k) as tf32
    for (int e = tid; e < 128 * 128; e += 256) {
        int j = e >> 7, k = e & 127;
        Ws[j * XS_STR + k] = f2tf32(W[j * GF + k]);
    }
    __syncthreads();

    float acc[4][8][4];
#pragma unroll
    for (int mt = 0; mt < 4; mt++)
#pragma unroll
        for (int nt = 0; nt < 8; nt++)
#pragma unroll
            for (int i = 0; i < 4; i++) acc[mt][nt][i] = 0.0f;

    const int q  = lane >> 2;   // 0..7
    const int t4 = lane & 3;    // 0..3

#pragma unroll 1
    for (int k0 = 0; k0 < 128; k0 += 8) {
        unsigned af[4][4];
#pragma unroll
        for (int mt = 0; mt < 4; mt++) {
            int r = wr * 64 + mt * 16 + q;
            af[mt][0] = Xs[r * XS_STR + k0 + t4];
            af[mt][1] = Xs[(r + 8) * XS_STR + k0 + t4];
            af[mt][2] = Xs[r * XS_STR + k0 + t4 + 4];
            af[mt][3] = Xs[(r + 8) * XS_STR + k0 + t4 + 4];
        }
        unsigned bf[8][2];
#pragma unroll
        for (int nt = 0; nt < 8; nt++) {
            int j = wc * 64 + nt * 8 + q;
            bf[nt][0] = Ws[j * XS_STR + k0 + t4];
            bf[nt][1] = Ws[j * XS_STR + k0 + t4 + 4];
        }
#pragma unroll
        for (int mt = 0; mt < 4; mt++)
#pragma unroll
            for (int nt = 0; nt < 8; nt++)
                mma_tf32(acc[mt][nt], af[mt], bf[nt], acc[mt][nt]);
    }

    // Epilogue: write xw and self-loop h = dinv^2 * xw
#pragma unroll
    for (int mt = 0; mt < 4; mt++) {
#pragma unroll
        for (int half = 0; half < 2; half++) {
            int grow = row0 + wr * 64 + mt * 16 + q + half * 8;
            if (grow < N) {
                float di   = g_deg[grow];
                float self = di * di;
#pragma unroll
                for (int nt = 0; nt < 8; nt++) {
                    int col = wc * 64 + nt * 8 + 2 * t4;
                    float2 v = make_float2(acc[mt][nt][2 * half],
                                           acc[mt][nt][2 * half + 1]);
                    *(float2*)&g_xw[(size_t)grow * GF + col] = v;
                    float2 hv = make_float2(v.x * self, v.y * self);
                    *(float2*)&h[(size_t)grow * GF + col] = hv;
                }
            }
        }
    }
}

// ---------------------------------------------------------------------------
// edge scatter: h[dst] += xw[src] * dinv[src]*dinv[dst]
// One warp per edge; float4 gather + vector RED (red.global.add.v4.f32).
__global__ __launch_bounds__(256) void k_edges(const int* __restrict__ src,
                                               const int* __restrict__ dst,
                                               float* __restrict__ h, int E) {
    long long t = (long long)blockIdx.x * blockDim.x + threadIdx.x;
    int e = (int)(t >> 5);
    if (e >= E) return;
    int lane = (int)(t & 31);
    int s = __ldg(src + e);
    int d = __ldg(dst + e);
    float norm = __ldg(&g_deg[s]) * __ldg(&g_deg[d]);
    float4 v = *(const float4*)(g_xw + (size_t)s * GF + lane * 4);
    float* hp = h + (size_t)d * GF + lane * 4;
    asm volatile("red.global.add.v4.f32 [%0], {%1, %2, %3, %4};"
                 :: "l"(hp), "f"(v.x * norm), "f"(v.y * norm),
                    "f"(v.z * norm), "f"(v.w * norm)
                 : "memory");
}

// ---------------------------------------------------------------------------
// epilogue: h = relu(agg + b_conv) in place; out = sigmoid(h . W_lin + b_lin)
__global__ __launch_bounds__(256) void k_final(float* __restrict__ h,
                                               const float* __restrict__ bconv,
                                               const float* __restrict__ wlin,
                                               const float* __restrict__ blin,
                                               float* __restrict__ out, int N) {
    int warp = (blockIdx.x * blockDim.x + threadIdx.x) >> 5;
    int lane = threadIdx.x & 31;
    if (warp >= N) return;
    size_t base = (size_t)warp * GF + lane * 4;
    float4 v = *(float4*)(h + base);
    float4 b = *(const float4*)(bconv + lane * 4);
    v.x = fmaxf(v.x + b.x, 0.0f);
    v.y = fmaxf(v.y + b.y, 0.0f);
    v.z = fmaxf(v.z + b.z, 0.0f);
    v.w = fmaxf(v.w + b.w, 0.0f);
    *(float4*)(h + base) = v;
    float4 w = *(const float4*)(wlin + lane * 4);
    float dot = v.x * w.x + v.y * w.y + v.z * w.z + v.w * w.w;
#pragma unroll
    for (int o = 16; o; o >>= 1) dot += __shfl_xor_sync(0xFFFFFFFFu, dot, o);
    if (lane == 0) {
        float z = dot + blin[0];
        out[warp] = 1.0f / (1.0f + expf(-z));
    }
}

// ---------------------------------------------------------------------------
extern "C" void kernel_launch(void* const* d_in, const int* in_sizes, int n_in,
                              void* d_out, int out_size) {
    const float* x  = (const float*)d_in[0];
    const int*   ei = (const int*)d_in[1];
    const float* Wc = (const float*)d_in[2];
    const float* bc = (const float*)d_in[3];
    const float* Wl = (const float*)d_in[4];
    const float* bl = (const float*)d_in[5];

    int N = in_sizes[0] / GF;
    int E = in_sizes[1] / 2;

    float* out = (float*)d_out;
    float* h   = out + N;          // (out, h) flattened: out first, then h
    const int* src = ei;
    const int* dst = ei + E;

    static bool attr_set = false;
    const int smem_bytes = (256 * XS_STR + 128 * XS_STR) * 4;  // 202752
    if (!attr_set) {
        cudaFuncSetAttribute(k_gemm_tf32,
                             cudaFuncAttributeMaxDynamicSharedMemorySize,
                             smem_bytes);
        attr_set = true;
    }

    k_deg_init<<<(N + 255) / 256, 256>>>(N);
    k_deg_count<<<(E + 255) / 256, 256>>>(dst, E);
    k_dinv<<<(N + 255) / 256, 256>>>(N);
    k_gemm_tf32<<<(N + 255) / 256, 256, smem_bytes>>>(x, Wc, h, N);

    long long tot = (long long)E * 32;
    k_edges<<<(unsigned)((tot + 255) / 256), 256>>>(src, dst, h, E);

    k_final<<<(N + 7) / 8, 256>>>(h, bc, Wl, bl, out, N);
}

// round 5
// speedup vs baseline: 1.8832x; 1.2133x over previous
#include <cuda_runtime.h>
#include <cuda_bf16.h>
#include <math.h>

#define GN 100000
#define GF 128
#define GE 640000

// Scratch (device globals — no allocation allowed)
__device__ float g_xw[(size_t)GN * GF];   // x @ W_conv^T
__device__ float g_deg[GN];               // degree -> dinv (in place)

// ---------------------------------------------------------------------------
__global__ void k_deg_init(int N) {
    int i = blockIdx.x * blockDim.x + threadIdx.x;
    if (i < N) g_deg[i] = 1.0f;
}

__global__ void k_deg_count(const int* __restrict__ dst, int E) {
    int e = blockIdx.x * blockDim.x + threadIdx.x;
    if (e < E) atomicAdd(&g_deg[dst[e]], 1.0f);
}

__global__ void k_dinv(int N) {
    int i = blockIdx.x * blockDim.x + threadIdx.x;
    if (i < N) g_deg[i] = rsqrtf(g_deg[i]);
}

// ---------------------------------------------------------------------------
// tf32 helpers
__device__ __forceinline__ unsigned f2tf32(float f) {
    unsigned u;
    asm("cvt.rna.tf32.f32 %0, %1;" : "=r"(u) : "f"(f));
    return u;
}

__device__ __forceinline__ void mma_tf32(float d[4], const unsigned a[4],
                                         const unsigned b[2], const float c[4]) {
    asm volatile(
        "mma.sync.aligned.m16n8k8.row.col.f32.tf32.tf32.f32 "
        "{%0,%1,%2,%3}, {%4,%5,%6,%7}, {%8,%9}, {%10,%11,%12,%13};\n"
        : "=f"(d[0]), "=f"(d[1]), "=f"(d[2]), "=f"(d[3])
        : "r"(a[0]), "r"(a[1]), "r"(a[2]), "r"(a[3]),
          "r"(b[0]), "r"(b[1]),
          "f"(c[0]), "f"(c[1]), "f"(c[2]), "f"(c[3]));
}

// ---------------------------------------------------------------------------
// GEMM: xw = x @ W^T via tf32 mma.sync.  Block tile 256 rows x 128 cols,
// full K=128 resident in smem.  512 threads / 16 warps, each warp 32x64.
// Also writes self-loop contribution dinv[i]^2 * xw[i] into h.
#define XS_STR 132
__global__ __launch_bounds__(512) void k_gemm_tf32(const float* __restrict__ x,
                                                   const float* __restrict__ W,
                                                   float* __restrict__ h, int N) {
    extern __shared__ unsigned smem[];
    unsigned* Xs = smem;                    // [256][132]
    unsigned* Ws = smem + 256 * XS_STR;     // [128][132]

    const int tid  = threadIdx.x;
    const int lane = tid & 31;
    const int wid  = tid >> 5;
    const int wr   = wid >> 1;   // warp row group 0..7  (32 rows each)
    const int wc   = wid & 1;    // warp col group 0..1  (64 cols each)
    const int row0 = blockIdx.x * 256;

    // Stage X tile (256x128) as tf32, float4 loads / uint4 stores
    for (int e = tid; e < 256 * 32; e += 512) {
        int r = e >> 5, c = (e & 31) * 4;
        int grow = row0 + r;
        float4 v = make_float4(0.f, 0.f, 0.f, 0.f);
        if (grow < N) v = *(const float4*)(x + (size_t)grow * GF + c);
        uint4 u = make_uint4(f2tf32(v.x), f2tf32(v.y), f2tf32(v.z), f2tf32(v.w));
        *(uint4*)&Xs[r * XS_STR + c] = u;
    }
    // Stage W (128x128, row = out feature j, col = k) as tf32
    for (int e = tid; e < 128 * 32; e += 512) {
        int j = e >> 5, c = (e & 31) * 4;
        float4 v = *(const float4*)(W + (size_t)j * GF + c);
        uint4 u = make_uint4(f2tf32(v.x), f2tf32(v.y), f2tf32(v.z), f2tf32(v.w));
        *(uint4*)&Ws[j * XS_STR + c] = u;
    }
    __syncthreads();

    float acc[2][8][4];
#pragma unroll
    for (int mt = 0; mt < 2; mt++)
#pragma unroll
        for (int nt = 0; nt < 8; nt++)
#pragma unroll
            for (int i = 0; i < 4; i++) acc[mt][nt][i] = 0.0f;

    const int q  = lane >> 2;   // 0..7
    const int t4 = lane & 3;    // 0..3

#pragma unroll 1
    for (int k0 = 0; k0 < 128; k0 += 8) {
        unsigned af[2][4];
#pragma unroll
        for (int mt = 0; mt < 2; mt++) {
            int r = wr * 32 + mt * 16 + q;
            af[mt][0] = Xs[r * XS_STR + k0 + t4];
            af[mt][1] = Xs[(r + 8) * XS_STR + k0 + t4];
            af[mt][2] = Xs[r * XS_STR + k0 + t4 + 4];
            af[mt][3] = Xs[(r + 8) * XS_STR + k0 + t4 + 4];
        }
        unsigned bf[8][2];
#pragma unroll
        for (int nt = 0; nt < 8; nt++) {
            int j = wc * 64 + nt * 8 + q;
            bf[nt][0] = Ws[j * XS_STR + k0 + t4];
            bf[nt][1] = Ws[j * XS_STR + k0 + t4 + 4];
        }
#pragma unroll
        for (int mt = 0; mt < 2; mt++)
#pragma unroll
            for (int nt = 0; nt < 8; nt++)
                mma_tf32(acc[mt][nt], af[mt], bf[nt], acc[mt][nt]);
    }

    // Epilogue: write xw and self-loop h = dinv^2 * xw
#pragma unroll
    for (int mt = 0; mt < 2; mt++) {
#pragma unroll
        for (int half = 0; half < 2; half++) {
            int grow = row0 + wr * 32 + mt * 16 + q + half * 8;
            if (grow < N) {
                float di   = g_deg[grow];
                float self = di * di;
#pragma unroll
                for (int nt = 0; nt < 8; nt++) {
                    int col = wc * 64 + nt * 8 + 2 * t4;
                    float2 v = make_float2(acc[mt][nt][2 * half],
                                           acc[mt][nt][2 * half + 1]);
                    *(float2*)&g_xw[(size_t)grow * GF + col] = v;
                    float2 hv = make_float2(v.x * self, v.y * self);
                    *(float2*)&h[(size_t)grow * GF + col] = hv;
                }
            }
        }
    }
}

// ---------------------------------------------------------------------------
// edge scatter: h[dst] += xw[src] * dinv[src]*dinv[dst]
// One warp per edge; float4 gather + vector RED (red.global.add.v4.f32).
__global__ __launch_bounds__(256) void k_edges(const int* __restrict__ src,
                                               const int* __restrict__ dst,
                                               float* __restrict__ h, int E) {
    long long t = (long long)blockIdx.x * blockDim.x + threadIdx.x;
    int e = (int)(t >> 5);
    if (e >= E) return;
    int lane = (int)(t & 31);
    int s = __ldg(src + e);
    int d = __ldg(dst + e);
    float norm = __ldg(&g_deg[s]) * __ldg(&g_deg[d]);
    float4 v = *(const float4*)(g_xw + (size_t)s * GF + lane * 4);
    float* hp = h + (size_t)d * GF + lane * 4;
    asm volatile("red.global.add.v4.f32 [%0], {%1, %2, %3, %4};"
                 :: "l"(hp), "f"(v.x * norm), "f"(v.y * norm),
                    "f"(v.z * norm), "f"(v.w * norm)
                 : "memory");
}

// ---------------------------------------------------------------------------
// epilogue: h = relu(agg + b_conv) in place; out = sigmoid(h . W_lin + b_lin)
__global__ __launch_bounds__(256) void k_final(float* __restrict__ h,
                                               const float* __restrict__ bconv,
                                               const float* __restrict__ wlin,
                                               const float* __restrict__ blin,
                                               float* __restrict__ out, int N) {
    int warp = (blockIdx.x * blockDim.x + threadIdx.x) >> 5;
    int lane = threadIdx.x & 31;
    if (warp >= N) return;
    size_t base = (size_t)warp * GF + lane * 4;
    float4 v = *(float4*)(h + base);
    float4 b = *(const float4*)(bconv + lane * 4);
    v.x = fmaxf(v.x + b.x, 0.0f);
    v.y = fmaxf(v.y + b.y, 0.0f);
    v.z = fmaxf(v.z + b.z, 0.0f);
    v.w = fmaxf(v.w + b.w, 0.0f);
    *(float4*)(h + base) = v;
    float4 w = *(const float4*)(wlin + lane * 4);
    float dot = v.x * w.x + v.y * w.y + v.z * w.z + v.w * w.w;
#pragma unroll
    for (int o = 16; o; o >>= 1) dot += __shfl_xor_sync(0xFFFFFFFFu, dot, o);
    if (lane == 0) {
        float z = dot + blin[0];
        out[warp] = 1.0f / (1.0f + expf(-z));
    }
}

// ---------------------------------------------------------------------------
extern "C" void kernel_launch(void* const* d_in, const int* in_sizes, int n_in,
                              void* d_out, int out_size) {
    const float* x  = (const float*)d_in[0];
    const int*   ei = (const int*)d_in[1];
    const float* Wc = (const float*)d_in[2];
    const float* bc = (const float*)d_in[3];
    const float* Wl = (const float*)d_in[4];
    const float* bl = (const float*)d_in[5];

    int N = in_sizes[0] / GF;
    int E = in_sizes[1] / 2;

    float* out = (float*)d_out;
    float* h   = out + N;          // (out, h) flattened: out first, then h
    const int* src = ei;
    const int* dst = ei + E;

    static bool attr_set = false;
    const int smem_bytes = (256 * XS_STR + 128 * XS_STR) * 4;  // 202752
    if (!attr_set) {
        cudaFuncSetAttribute(k_gemm_tf32,
                             cudaFuncAttributeMaxDynamicSharedMemorySize,
                             smem_bytes);
        attr_set = true;
    }

    k_deg_init<<<(N + 255) / 256, 256>>>(N);
    k_deg_count<<<(E + 255) / 256, 256>>>(dst, E);
    k_dinv<<<(N + 255) / 256, 256>>>(N);
    k_gemm_tf32<<<(N + 255) / 256, 512, smem_bytes>>>(x, Wc, h, N);

    long long tot = (long long)E * 32;
    k_edges<<<(unsigned)((tot + 255) / 256), 256>>>(src, dst, h, E);

    k_final<<<(N + 7) / 8, 256>>>(h, bc, Wl, bl, out, N);
}

// round 6
// speedup vs baseline: 2.5605x; 1.3597x over previous
#include <cuda_runtime.h>
#include <cuda_bf16.h>
#include <math.h>

#define GN 100000
#define GF 128
#define GE 640000
#define SCAN_BLK 1024
#define NPART ((GN + SCAN_BLK - 1) / SCAN_BLK)   // 98

// Scratch (device globals — no allocation allowed)
__device__ float g_xw[(size_t)GN * GF];   // x @ W_conv^T
__device__ float g_dinv[GN];              // rsqrt(deg)
__device__ int   g_cnt[GN];               // in-degree (edges only)
__device__ int   g_start[GN + 1];         // CSR segment starts
__device__ int   g_cursor[GN];            // bin cursors
__device__ int   g_part[NPART];           // scan partials
__device__ int   g_ssrc[GE];              // src sorted by dst
__device__ float g_snorm[GE];             // norm sorted by dst

// ---------------------------------------------------------------------------
__global__ void k_zero(int N) {
    int i = blockIdx.x * blockDim.x + threadIdx.x;
    if (i < N) g_cnt[i] = 0;
}

__global__ void k_cnt(const int* __restrict__ dst, int E) {
    int e = blockIdx.x * blockDim.x + threadIdx.x;
    if (e < E) atomicAdd(&g_cnt[dst[e]], 1);
}

__global__ void k_dinv(int N) {
    int i = blockIdx.x * blockDim.x + threadIdx.x;
    if (i < N) g_dinv[i] = rsqrtf((float)(g_cnt[i] + 1));  // +1 self loop
}

// ---------------------------------------------------------------------------
// Exclusive scan over g_cnt -> g_start (3-pass)
__global__ __launch_bounds__(SCAN_BLK) void k_scan1(int N) {
    __shared__ int wsum[32];
    int tid  = threadIdx.x;
    int lane = tid & 31, wid = tid >> 5;
    int i = blockIdx.x * SCAN_BLK + tid;
    int v = (i < N) ? g_cnt[i] : 0;
    int x = v;
#pragma unroll
    for (int o = 1; o < 32; o <<= 1) {
        int y = __shfl_up_sync(0xFFFFFFFFu, x, o);
        if (lane >= o) x += y;
    }
    if (lane == 31) wsum[wid] = x;
    __syncthreads();
    if (wid == 0) {
        int s = wsum[lane];
#pragma unroll
        for (int o = 1; o < 32; o <<= 1) {
            int y = __shfl_up_sync(0xFFFFFFFFu, s, o);
            if (lane >= o) s += y;
        }
        wsum[lane] = s;   // inclusive warp-sum prefix
    }
    __syncthreads();
    int incl = x + (wid > 0 ? wsum[wid - 1] : 0);
    if (i < N) g_start[i] = incl - v;           // exclusive
    if (tid == SCAN_BLK - 1) g_part[blockIdx.x] = incl;  // block total
}

__global__ __launch_bounds__(128) void k_scan2() {
    __shared__ int s[128];
    int t = threadIdx.x;
    int v = (t < NPART) ? g_part[t] : 0;
    s[t] = v;
    __syncthreads();
#pragma unroll
    for (int o = 1; o < 128; o <<= 1) {
        int y = (t >= o) ? s[t - o] : 0;
        __syncthreads();
        s[t] += y;
        __syncthreads();
    }
    if (t < NPART) g_part[t] = s[t] - v;        // exclusive
}

__global__ void k_scan3(int N, int E) {
    int i = blockIdx.x * blockDim.x + threadIdx.x;
    if (i < N) {
        int st = g_start[i] + g_part[i >> 10];
        g_start[i]  = st;
        g_cursor[i] = st;
    }
    if (i == 0) g_start[N] = E;
}

// ---------------------------------------------------------------------------
// bin: place each edge into its dst segment with precomputed norm
__global__ void k_bin(const int* __restrict__ src, const int* __restrict__ dst,
                      int E) {
    int e = blockIdx.x * blockDim.x + threadIdx.x;
    if (e >= E) return;
    int s = src[e], d = dst[e];
    int pos = atomicAdd(&g_cursor[d], 1);
    g_ssrc[pos]  = s;
    g_snorm[pos] = g_dinv[s] * g_dinv[d];
}

// ---------------------------------------------------------------------------
// tf32 helpers
__device__ __forceinline__ unsigned f2tf32(float f) {
    unsigned u;
    asm("cvt.rna.tf32.f32 %0, %1;" : "=r"(u) : "f"(f));
    return u;
}

__device__ __forceinline__ void mma_tf32(float d[4], const unsigned a[4],
                                         const unsigned b[2], const float c[4]) {
    asm volatile(
        "mma.sync.aligned.m16n8k8.row.col.f32.tf32.tf32.f32 "
        "{%0,%1,%2,%3}, {%4,%5,%6,%7}, {%8,%9}, {%10,%11,%12,%13};\n"
        : "=f"(d[0]), "=f"(d[1]), "=f"(d[2]), "=f"(d[3])
        : "r"(a[0]), "r"(a[1]), "r"(a[2]), "r"(a[3]),
          "r"(b[0]), "r"(b[1]),
          "f"(c[0]), "f"(c[1]), "f"(c[2]), "f"(c[3]));
}

// ---------------------------------------------------------------------------
// GEMM: xw = x @ W^T via tf32 mma.sync.  256x128 block tile, K=128 resident,
// 512 threads / 16 warps (32x64 per warp).  Writes g_xw only.
#define XS_STR 132
__global__ __launch_bounds__(512) void k_gemm_tf32(const float* __restrict__ x,
                                                   const float* __restrict__ W,
                                                   int N) {
    extern __shared__ unsigned smem[];
    unsigned* Xs = smem;                    // [256][132]
    unsigned* Ws = smem + 256 * XS_STR;     // [128][132]

    const int tid  = threadIdx.x;
    const int lane = tid & 31;
    const int wid  = tid >> 5;
    const int wr   = wid >> 1;
    const int wc   = wid & 1;
    const int row0 = blockIdx.x * 256;

    for (int e = tid; e < 256 * 32; e += 512) {
        int r = e >> 5, c = (e & 31) * 4;
        int grow = row0 + r;
        float4 v = make_float4(0.f, 0.f, 0.f, 0.f);
        if (grow < N) v = *(const float4*)(x + (size_t)grow * GF + c);
        uint4 u = make_uint4(f2tf32(v.x), f2tf32(v.y), f2tf32(v.z), f2tf32(v.w));
        *(uint4*)&Xs[r * XS_STR + c] = u;
    }
    for (int e = tid; e < 128 * 32; e += 512) {
        int j = e >> 5, c = (e & 31) * 4;
        float4 v = *(const float4*)(W + (size_t)j * GF + c);
        uint4 u = make_uint4(f2tf32(v.x), f2tf32(v.y), f2tf32(v.z), f2tf32(v.w));
        *(uint4*)&Ws[j * XS_STR + c] = u;
    }
    __syncthreads();

    float acc[2][8][4];
#pragma unroll
    for (int mt = 0; mt < 2; mt++)
#pragma unroll
        for (int nt = 0; nt < 8; nt++)
#pragma unroll
            for (int i = 0; i < 4; i++) acc[mt][nt][i] = 0.0f;

    const int q  = lane >> 2;
    const int t4 = lane & 3;

#pragma unroll 1
    for (int k0 = 0; k0 < 128; k0 += 8) {
        unsigned af[2][4];
#pragma unroll
        for (int mt = 0; mt < 2; mt++) {
            int r = wr * 32 + mt * 16 + q;
            af[mt][0] = Xs[r * XS_STR + k0 + t4];
            af[mt][1] = Xs[(r + 8) * XS_STR + k0 + t4];
            af[mt][2] = Xs[r * XS_STR + k0 + t4 + 4];
            af[mt][3] = Xs[(r + 8) * XS_STR + k0 + t4 + 4];
        }
        unsigned bf[8][2];
#pragma unroll
        for (int nt = 0; nt < 8; nt++) {
            int j = wc * 64 + nt * 8 + q;
            bf[nt][0] = Ws[j * XS_STR + k0 + t4];
            bf[nt][1] = Ws[j * XS_STR + k0 + t4 + 4];
        }
#pragma unroll
        for (int mt = 0; mt < 2; mt++)
#pragma unroll
            for (int nt = 0; nt < 8; nt++)
                mma_tf32(acc[mt][nt], af[mt], bf[nt], acc[mt][nt]);
    }

#pragma unroll
    for (int mt = 0; mt < 2; mt++) {
#pragma unroll
        for (int half = 0; half < 2; half++) {
            int grow = row0 + wr * 32 + mt * 16 + q + half * 8;
            if (grow < N) {
#pragma unroll
                for (int nt = 0; nt < 8; nt++) {
                    int col = wc * 64 + nt * 8 + 2 * t4;
                    float2 v = make_float2(acc[mt][nt][2 * half],
                                           acc[mt][nt][2 * half + 1]);
                    *(float2*)&g_xw[(size_t)grow * GF + col] = v;
                }
            }
        }
    }
}

// ---------------------------------------------------------------------------
// Fused aggregate + bias + relu + linear + sigmoid.  One warp per node.
// acc = dinv[i]^2 * xw[i] + sum_seg norm * xw[src];  h = relu(acc + b);
// out = sigmoid(h . wlin + bl).  No atomics.
__global__ __launch_bounds__(256) void k_agg(const float* __restrict__ bconv,
                                             const float* __restrict__ wlin,
                                             const float* __restrict__ blin,
                                             float* __restrict__ h,
                                             float* __restrict__ out, int N) {
    int node = (blockIdx.x * blockDim.x + threadIdx.x) >> 5;
    int lane = threadIdx.x & 31;
    if (node >= N) return;

    const float* myrow = g_xw + (size_t)node * GF + lane * 4;
    float di = g_dinv[node];
    float self = di * di;
    float4 v = *(const float4*)myrow;
    float4 acc = make_float4(v.x * self, v.y * self, v.z * self, v.w * self);

    int p0 = g_start[node], p1 = g_start[node + 1];
    for (int p = p0; p < p1; p++) {
        int   s   = __ldg(&g_ssrc[p]);
        float nrm = __ldg(&g_snorm[p]);
        float4 m = *(const float4*)(g_xw + (size_t)s * GF + lane * 4);
        acc.x = fmaf(m.x, nrm, acc.x);
        acc.y = fmaf(m.y, nrm, acc.y);
        acc.z = fmaf(m.z, nrm, acc.z);
        acc.w = fmaf(m.w, nrm, acc.w);
    }

    float4 b = *(const float4*)(bconv + lane * 4);
    acc.x = fmaxf(acc.x + b.x, 0.0f);
    acc.y = fmaxf(acc.y + b.y, 0.0f);
    acc.z = fmaxf(acc.z + b.z, 0.0f);
    acc.w = fmaxf(acc.w + b.w, 0.0f);
    *(float4*)(h + (size_t)node * GF + lane * 4) = acc;

    float4 w = *(const float4*)(wlin + lane * 4);
    float dot = acc.x * w.x + acc.y * w.y + acc.z * w.z + acc.w * w.w;
#pragma unroll
    for (int o = 16; o; o >>= 1) dot += __shfl_xor_sync(0xFFFFFFFFu, dot, o);
    if (lane == 0) {
        float z = dot + blin[0];
        out[node] = 1.0f / (1.0f + expf(-z));
    }
}

// ---------------------------------------------------------------------------
extern "C" void kernel_launch(void* const* d_in, const int* in_sizes, int n_in,
                              void* d_out, int out_size) {
    const float* x  = (const float*)d_in[0];
    const int*   ei = (const int*)d_in[1];
    const float* Wc = (const float*)d_in[2];
    const float* bc = (const float*)d_in[3];
    const float* Wl = (const float*)d_in[4];
    const float* bl = (const float*)d_in[5];

    int N = in_sizes[0] / GF;
    int E = in_sizes[1] / 2;

    float* out = (float*)d_out;
    float* h   = out + N;
    const int* src = ei;
    const int* dst = ei + E;

    static bool attr_set = false;
    const int smem_bytes = (256 * XS_STR + 128 * XS_STR) * 4;  // 202752
    if (!attr_set) {
        cudaFuncSetAttribute(k_gemm_tf32,
                             cudaFuncAttributeMaxDynamicSharedMemorySize,
                             smem_bytes);
        attr_set = true;
    }

    // CSR build
    k_zero<<<(N + 255) / 256, 256>>>(N);
    k_cnt<<<(E + 255) / 256, 256>>>(dst, E);
    k_dinv<<<(N + 255) / 256, 256>>>(N);
    k_scan1<<<NPART, SCAN_BLK>>>(N);
    k_scan2<<<1, 128>>>();
    k_scan3<<<(N + 255) / 256, 256>>>(N, E);
    k_bin<<<(E + 255) / 256, 256>>>(src, dst, E);

    // GEMM (independent of CSR build except stream order)
    k_gemm_tf32<<<(N + 255) / 256, 512, smem_bytes>>>(x, Wc, N);

    // Fused aggregate + epilogue
    k_agg<<<(N * 32 + 255) / 256, 256>>>(bc, Wl, bl, h, out, N);
}

// round 7
// speedup vs baseline: 2.9948x; 1.1696x over previous
#include <cuda_runtime.h>
#include <cuda_bf16.h>
#include <math.h>

#define GN 100000
#define GF 128
#define GE 640000
#define SCAN_BLK 1024
#define NPART ((GN + SCAN_BLK - 1) / SCAN_BLK)   // 98

// Scratch (device globals — no allocation allowed)
__device__ float g_xw[(size_t)GN * GF];   // x @ W_conv^T
__device__ float g_dinv[GN];              // rsqrt(deg)
__device__ int   g_cnt[GN];               // in-degree (edges only)
__device__ int   g_start[GN + 1];         // CSR segment starts
__device__ int   g_cursor[GN];            // bin cursors
__device__ int   g_part[NPART];           // scan partials
__device__ int   g_ssrc[GE];              // src sorted by dst
__device__ float g_snorm[GE];             // norm sorted by dst

// ---------------------------------------------------------------------------
__global__ void k_zero(int N) {
    int i = blockIdx.x * blockDim.x + threadIdx.x;
    if (i < N) g_cnt[i] = 0;
}

__global__ void k_cnt(const int* __restrict__ dst, int E) {
    int e = blockIdx.x * blockDim.x + threadIdx.x;
    if (e < E) atomicAdd(&g_cnt[dst[e]], 1);
}

__global__ void k_dinv(int N) {
    int i = blockIdx.x * blockDim.x + threadIdx.x;
    if (i < N) g_dinv[i] = rsqrtf((float)(g_cnt[i] + 1));  // +1 self loop
}

// ---------------------------------------------------------------------------
// Exclusive scan over g_cnt -> g_start (3-pass)
__global__ __launch_bounds__(SCAN_BLK) void k_scan1(int N) {
    __shared__ int wsum[32];
    int tid  = threadIdx.x;
    int lane = tid & 31, wid = tid >> 5;
    int i = blockIdx.x * SCAN_BLK + tid;
    int v = (i < N) ? g_cnt[i] : 0;
    int x = v;
#pragma unroll
    for (int o = 1; o < 32; o <<= 1) {
        int y = __shfl_up_sync(0xFFFFFFFFu, x, o);
        if (lane >= o) x += y;
    }
    if (lane == 31) wsum[wid] = x;
    __syncthreads();
    if (wid == 0) {
        int s = wsum[lane];
#pragma unroll
        for (int o = 1; o < 32; o <<= 1) {
            int y = __shfl_up_sync(0xFFFFFFFFu, s, o);
            if (lane >= o) s += y;
        }
        wsum[lane] = s;
    }
    __syncthreads();
    int incl = x + (wid > 0 ? wsum[wid - 1] : 0);
    if (i < N) g_start[i] = incl - v;
    if (tid == SCAN_BLK - 1) g_part[blockIdx.x] = incl;
}

__global__ __launch_bounds__(128) void k_scan2() {
    __shared__ int s[128];
    int t = threadIdx.x;
    int v = (t < NPART) ? g_part[t] : 0;
    s[t] = v;
    __syncthreads();
#pragma unroll
    for (int o = 1; o < 128; o <<= 1) {
        int y = (t >= o) ? s[t - o] : 0;
        __syncthreads();
        s[t] += y;
        __syncthreads();
    }
    if (t < NPART) g_part[t] = s[t] - v;
}

__global__ void k_scan3(int N, int E) {
    int i = blockIdx.x * blockDim.x + threadIdx.x;
    if (i < N) {
        int st = g_start[i] + g_part[i >> 10];
        g_start[i]  = st;
        g_cursor[i] = st;
    }
    if (i == 0) g_start[N] = E;
}

// ---------------------------------------------------------------------------
__global__ void k_bin(const int* __restrict__ src, const int* __restrict__ dst,
                      int E) {
    int e = blockIdx.x * blockDim.x + threadIdx.x;
    if (e >= E) return;
    int s = src[e], d = dst[e];
    int pos = atomicAdd(&g_cursor[d], 1);
    g_ssrc[pos]  = s;
    g_snorm[pos] = g_dinv[s] * g_dinv[d];
}

// ---------------------------------------------------------------------------
// tf32 helpers
__device__ __forceinline__ unsigned f2tf32(float f) {
    unsigned u;
    asm("cvt.rna.tf32.f32 %0, %1;" : "=r"(u) : "f"(f));
    return u;
}

__device__ __forceinline__ void mma_tf32(float d[4], const unsigned a[4],
                                         const unsigned b[2], const float c[4]) {
    asm volatile(
        "mma.sync.aligned.m16n8k8.row.col.f32.tf32.tf32.f32 "
        "{%0,%1,%2,%3}, {%4,%5,%6,%7}, {%8,%9}, {%10,%11,%12,%13};\n"
        : "=f"(d[0]), "=f"(d[1]), "=f"(d[2]), "=f"(d[3])
        : "r"(a[0]), "r"(a[1]), "r"(a[2]), "r"(a[3]),
          "r"(b[0]), "r"(b[1]),
          "f"(c[0]), "f"(c[1]), "f"(c[2]), "f"(c[3]));
}

__device__ __forceinline__ void cp16(float* smem_ptr, const float* gptr,
                                     bool valid) {
    unsigned saddr = (unsigned)__cvta_generic_to_shared(smem_ptr);
    int sz = valid ? 16 : 0;
    asm volatile("cp.async.cg.shared.global [%0], [%1], 16, %2;\n"
                 :: "r"(saddr), "l"(gptr), "r"(sz));
}

// ---------------------------------------------------------------------------
// GEMM: xw = x @ W^T via tf32 mma.sync with cp.async double-buffered
// K-chunk pipeline.  Block tile 256x128, K chunked by 32, 512 threads,
// 16 warps of 32x64.  Writes g_xw only.
#define XCH 32
#define XST 36    // Xs row stride (floats)
#define WST 132   // Ws row stride (tf32 words)
__global__ __launch_bounds__(512) void k_gemm_tf32(const float* __restrict__ x,
                                                   const float* __restrict__ W,
                                                   int N) {
    extern __shared__ float smf[];
    float* Xs = smf;                                    // [2][256][36]
    unsigned* Ws = (unsigned*)(smf + 2 * 256 * XST);    // [128][132]

    const int tid  = threadIdx.x;
    const int lane = tid & 31;
    const int wid  = tid >> 5;
    const int wr   = wid >> 1;   // 0..7 (32 rows)
    const int wc   = wid & 1;    // 0..1 (64 cols)
    const int row0 = blockIdx.x * 256;

    // stage one 256x32 X chunk into buffer buf via cp.async (fp32, zfill OOB)
    auto stage = [&](int ch, int buf) {
        float* base = Xs + buf * 256 * XST;
#pragma unroll
        for (int e = tid; e < 2048; e += 512) {
            int r = e >> 3, c4 = (e & 7) * 4;
            int grow = row0 + r;
            cp16(base + r * XST + c4,
                 x + (size_t)grow * GF + ch * XCH + c4, grow < N);
        }
        asm volatile("cp.async.commit_group;\n");
    };

    stage(0, 0);
    stage(1, 1);

    // stage W (128x128) as tf32 with regular loads (overlaps the cp.asyncs)
    for (int e = tid; e < 128 * 32; e += 512) {
        int j = e >> 5, c = (e & 31) * 4;
        float4 v = *(const float4*)(W + (size_t)j * GF + c);
        uint4 u = make_uint4(f2tf32(v.x), f2tf32(v.y), f2tf32(v.z), f2tf32(v.w));
        *(uint4*)&Ws[j * WST + c] = u;
    }
    asm volatile("cp.async.wait_group 1;\n");   // chunk 0 resident
    __syncthreads();

    float acc[2][8][4];
#pragma unroll
    for (int mt = 0; mt < 2; mt++)
#pragma unroll
        for (int nt = 0; nt < 8; nt++)
#pragma unroll
            for (int i = 0; i < 4; i++) acc[mt][nt][i] = 0.0f;

    const int q  = lane >> 2;
    const int t4 = lane & 3;

#pragma unroll
    for (int ch = 0; ch < 4; ch++) {
        const float* xb = Xs + (ch & 1) * 256 * XST;
#pragma unroll
        for (int kk = 0; kk < XCH; kk += 8) {
            unsigned af[2][4];
#pragma unroll
            for (int mt = 0; mt < 2; mt++) {
                int r = wr * 32 + mt * 16 + q;
                af[mt][0] = f2tf32(xb[r * XST + kk + t4]);
                af[mt][1] = f2tf32(xb[(r + 8) * XST + kk + t4]);
                af[mt][2] = f2tf32(xb[r * XST + kk + t4 + 4]);
                af[mt][3] = f2tf32(xb[(r + 8) * XST + kk + t4 + 4]);
            }
            int k0 = ch * XCH + kk;
            unsigned bf[8][2];
#pragma unroll
            for (int nt = 0; nt < 8; nt++) {
                int j = wc * 64 + nt * 8 + q;
                bf[nt][0] = Ws[j * WST + k0 + t4];
                bf[nt][1] = Ws[j * WST + k0 + t4 + 4];
            }
#pragma unroll
            for (int mt = 0; mt < 2; mt++)
#pragma unroll
                for (int nt = 0; nt < 8; nt++)
                    mma_tf32(acc[mt][nt], af[mt], bf[nt], acc[mt][nt]);
        }
        // pipeline bookkeeping
        if (ch == 0) {
            __syncthreads();
            stage(2, 0);
            asm volatile("cp.async.wait_group 1;\n");  // chunk 1 resident
            __syncthreads();
        } else if (ch == 1) {
            __syncthreads();
            stage(3, 1);
            asm volatile("cp.async.wait_group 1;\n");  // chunk 2 resident
            __syncthreads();
        } else if (ch == 2) {
            __syncthreads();
            asm volatile("cp.async.wait_group 0;\n");  // chunk 3 resident
            __syncthreads();
        }
    }

#pragma unroll
    for (int mt = 0; mt < 2; mt++) {
#pragma unroll
        for (int half = 0; half < 2; half++) {
            int grow = row0 + wr * 32 + mt * 16 + q + half * 8;
            if (grow < N) {
#pragma unroll
                for (int nt = 0; nt < 8; nt++) {
                    int col = wc * 64 + nt * 8 + 2 * t4;
                    float2 v = make_float2(acc[mt][nt][2 * half],
                                           acc[mt][nt][2 * half + 1]);
                    *(float2*)&g_xw[(size_t)grow * GF + col] = v;
                }
            }
        }
    }
}

// ---------------------------------------------------------------------------
// Fused aggregate + bias + relu + linear + sigmoid.  One warp per node.
__global__ __launch_bounds__(256) void k_agg(const float* __restrict__ bconv,
                                             const float* __restrict__ wlin,
                                             const float* __restrict__ blin,
                                             float* __restrict__ h,
                                             float* __restrict__ out, int N) {
    int node = (blockIdx.x * blockDim.x + threadIdx.x) >> 5;
    int lane = threadIdx.x & 31;
    if (node >= N) return;

    const float* myrow = g_xw + (size_t)node * GF + lane * 4;
    float di = g_dinv[node];
    float self = di * di;
    float4 v = *(const float4*)myrow;
    float4 acc = make_float4(v.x * self, v.y * self, v.z * self, v.w * self);

    int p0 = g_start[node], p1 = g_start[node + 1];
    for (int p = p0; p < p1; p++) {
        int   s   = __ldg(&g_ssrc[p]);
        float nrm = __ldg(&g_snorm[p]);
        float4 m = *(const float4*)(g_xw + (size_t)s * GF + lane * 4);
        acc.x = fmaf(m.x, nrm, acc.x);
        acc.y = fmaf(m.y, nrm, acc.y);
        acc.z = fmaf(m.z, nrm, acc.z);
        acc.w = fmaf(m.w, nrm, acc.w);
    }

    float4 b = *(const float4*)(bconv + lane * 4);
    acc.x = fmaxf(acc.x + b.x, 0.0f);
    acc.y = fmaxf(acc.y + b.y, 0.0f);
    acc.z = fmaxf(acc.z + b.z, 0.0f);
    acc.w = fmaxf(acc.w + b.w, 0.0f);
    *(float4*)(h + (size_t)node * GF + lane * 4) = acc;

    float4 w = *(const float4*)(wlin + lane * 4);
    float dot = acc.x * w.x + acc.y * w.y + acc.z * w.z + acc.w * w.w;
#pragma unroll
    for (int o = 16; o; o >>= 1) dot += __shfl_xor_sync(0xFFFFFFFFu, dot, o);
    if (lane == 0) {
        float z = dot + blin[0];
        out[node] = 1.0f / (1.0f + expf(-z));
    }
}

// ---------------------------------------------------------------------------
extern "C" void kernel_launch(void* const* d_in, const int* in_sizes, int n_in,
                              void* d_out, int out_size) {
    const float* x  = (const float*)d_in[0];
    const int*   ei = (const int*)d_in[1];
    const float* Wc = (const float*)d_in[2];
    const float* bc = (const float*)d_in[3];
    const float* Wl = (const float*)d_in[4];
    const float* bl = (const float*)d_in[5];

    int N = in_sizes[0] / GF;
    int E = in_sizes[1] / 2;

    float* out = (float*)d_out;
    float* h   = out + N;
    const int* src = ei;
    const int* dst = ei + E;

    static bool attr_set = false;
    const int smem_bytes = (2 * 256 * XST + 128 * WST) * 4;  // 141312
    if (!attr_set) {
        cudaFuncSetAttribute(k_gemm_tf32,
                             cudaFuncAttributeMaxDynamicSharedMemorySize,
                             smem_bytes);
        attr_set = true;
    }

    // CSR build
    k_zero<<<(N + 255) / 256, 256>>>(N);
    k_cnt<<<(E + 255) / 256, 256>>>(dst, E);
    k_dinv<<<(N + 255) / 256, 256>>>(N);
    k_scan1<<<NPART, SCAN_BLK>>>(N);
    k_scan2<<<1, 128>>>();
    k_scan3<<<(N + 255) / 256, 256>>>(N, E);
    k_bin<<<(E + 255) / 256, 256>>>(src, dst, E);

    // GEMM
    k_gemm_tf32<<<(N + 255) / 256, 512, smem_bytes>>>(x, Wc, N);

    // Fused aggregate + epilogue
    k_agg<<<(N * 32 + 255) / 256, 256>>>(bc, Wl, bl, h, out, N);
}

// round 8
// speedup vs baseline: 3.3664x; 1.1241x over previous
#include <cuda_runtime.h>
#include <cuda_bf16.h>
#include <math.h>

#define GN 100000
#define GF 128
#define GE 640000
#define SCAN_BLK 1024
#define NPART ((GN + SCAN_BLK - 1) / SCAN_BLK)   // 98

// Scratch (device globals — no allocation allowed)
__device__ float g_xw[(size_t)GN * GF];   // x @ W_conv^T
__device__ float g_dinv[GN];              // rsqrt(deg)
__device__ int   g_cnt[GN];               // in-degree (edges only)
__device__ int   g_start[GN + 1];         // CSR segment starts
__device__ int   g_cursor[GN];            // bin cursors
__device__ int   g_part[NPART];           // scan partials
__device__ int   g_ssrc[GE];              // src sorted by dst
__device__ float g_snorm[GE];             // norm sorted by dst

// ---------------------------------------------------------------------------
__global__ void k_zero(int N) {
    int i = blockIdx.x * blockDim.x + threadIdx.x;
    if (i < N) g_cnt[i] = 0;
}

__global__ void k_cnt(const int* __restrict__ dst, int E) {
    int e = blockIdx.x * blockDim.x + threadIdx.x;
    if (e < E) atomicAdd(&g_cnt[dst[e]], 1);
}

// ---------------------------------------------------------------------------
// Exclusive scan over g_cnt -> g_start; also computes dinv (fused).
__global__ __launch_bounds__(SCAN_BLK) void k_scan1(int N) {
    __shared__ int wsum[32];
    int tid  = threadIdx.x;
    int lane = tid & 31, wid = tid >> 5;
    int i = blockIdx.x * SCAN_BLK + tid;
    int v = (i < N) ? g_cnt[i] : 0;
    if (i < N) g_dinv[i] = rsqrtf((float)(v + 1));  // +1 self loop (fused)
    int x = v;
#pragma unroll
    for (int o = 1; o < 32; o <<= 1) {
        int y = __shfl_up_sync(0xFFFFFFFFu, x, o);
        if (lane >= o) x += y;
    }
    if (lane == 31) wsum[wid] = x;
    __syncthreads();
    if (wid == 0) {
        int s = wsum[lane];
#pragma unroll
        for (int o = 1; o < 32; o <<= 1) {
            int y = __shfl_up_sync(0xFFFFFFFFu, s, o);
            if (lane >= o) s += y;
        }
        wsum[lane] = s;
    }
    __syncthreads();
    int incl = x + (wid > 0 ? wsum[wid - 1] : 0);
    if (i < N) g_start[i] = incl - v;
    if (tid == SCAN_BLK - 1) g_part[blockIdx.x] = incl;
}

__global__ __launch_bounds__(128) void k_scan2() {
    __shared__ int s[128];
    int t = threadIdx.x;
    int v = (t < NPART) ? g_part[t] : 0;
    s[t] = v;
    __syncthreads();
#pragma unroll
    for (int o = 1; o < 128; o <<= 1) {
        int y = (t >= o) ? s[t - o] : 0;
        __syncthreads();
        s[t] += y;
        __syncthreads();
    }
    if (t < NPART) g_part[t] = s[t] - v;
}

__global__ void k_scan3(int N, int E) {
    int i = blockIdx.x * blockDim.x + threadIdx.x;
    if (i < N) {
        int st = g_start[i] + g_part[i >> 10];
        g_start[i]  = st;
        g_cursor[i] = st;
    }
    if (i == 0) g_start[N] = E;
}

// ---------------------------------------------------------------------------
__global__ void k_bin(const int* __restrict__ src, const int* __restrict__ dst,
                      int E) {
    int e = blockIdx.x * blockDim.x + threadIdx.x;
    if (e >= E) return;
    int s = src[e], d = dst[e];
    int pos = atomicAdd(&g_cursor[d], 1);
    g_ssrc[pos]  = s;
    g_snorm[pos] = g_dinv[s] * g_dinv[d];
}

// ---------------------------------------------------------------------------
// tf32 helpers
__device__ __forceinline__ unsigned f2tf32(float f) {
    unsigned u;
    asm("cvt.rna.tf32.f32 %0, %1;" : "=r"(u) : "f"(f));
    return u;
}

__device__ __forceinline__ void mma_tf32(float d[4], const unsigned a[4],
                                         const unsigned b[2], const float c[4]) {
    asm volatile(
        "mma.sync.aligned.m16n8k8.row.col.f32.tf32.tf32.f32 "
        "{%0,%1,%2,%3}, {%4,%5,%6,%7}, {%8,%9}, {%10,%11,%12,%13};\n"
        : "=f"(d[0]), "=f"(d[1]), "=f"(d[2]), "=f"(d[3])
        : "r"(a[0]), "r"(a[1]), "r"(a[2]), "r"(a[3]),
          "r"(b[0]), "r"(b[1]),
          "f"(c[0]), "f"(c[1]), "f"(c[2]), "f"(c[3]));
}

__device__ __forceinline__ void cp16(float* smem_ptr, const float* gptr,
                                     bool valid) {
    unsigned saddr = (unsigned)__cvta_generic_to_shared(smem_ptr);
    int sz = valid ? 16 : 0;
    asm volatile("cp.async.cg.shared.global [%0], [%1], 16, %2;\n"
                 :: "r"(saddr), "l"(gptr), "r"(sz));
}

// ---------------------------------------------------------------------------
// GEMM: xw = x @ W^T via tf32 mma.sync with cp.async double-buffered
// K-chunk pipeline.  Block tile 256x128, K chunked by 32, 512 threads,
// 16 warps of 32x64.  Writes g_xw only.
#define XCH 32
#define XST 36    // Xs row stride (floats)
#define WST 132   // Ws row stride (tf32 words)
__global__ __launch_bounds__(512) void k_gemm_tf32(const float* __restrict__ x,
                                                   const float* __restrict__ W,
                                                   int N) {
    extern __shared__ float smf[];
    float* Xs = smf;                                    // [2][256][36]
    unsigned* Ws = (unsigned*)(smf + 2 * 256 * XST);    // [128][132]

    const int tid  = threadIdx.x;
    const int lane = tid & 31;
    const int wid  = tid >> 5;
    const int wr   = wid >> 1;   // 0..7 (32 rows)
    const int wc   = wid & 1;    // 0..1 (64 cols)
    const int row0 = blockIdx.x * 256;

    auto stage = [&](int ch, int buf) {
        float* base = Xs + buf * 256 * XST;
#pragma unroll
        for (int e = tid; e < 2048; e += 512) {
            int r = e >> 3, c4 = (e & 7) * 4;
            int grow = row0 + r;
            cp16(base + r * XST + c4,
                 x + (size_t)grow * GF + ch * XCH + c4, grow < N);
        }
        asm volatile("cp.async.commit_group;\n");
    };

    stage(0, 0);
    stage(1, 1);

    for (int e = tid; e < 128 * 32; e += 512) {
        int j = e >> 5, c = (e & 31) * 4;
        float4 v = *(const float4*)(W + (size_t)j * GF + c);
        uint4 u = make_uint4(f2tf32(v.x), f2tf32(v.y), f2tf32(v.z), f2tf32(v.w));
        *(uint4*)&Ws[j * WST + c] = u;
    }
    asm volatile("cp.async.wait_group 1;\n");
    __syncthreads();

    float acc[2][8][4];
#pragma unroll
    for (int mt = 0; mt < 2; mt++)
#pragma unroll
        for (int nt = 0; nt < 8; nt++)
#pragma unroll
            for (int i = 0; i < 4; i++) acc[mt][nt][i] = 0.0f;

    const int q  = lane >> 2;
    const int t4 = lane & 3;

#pragma unroll
    for (int ch = 0; ch < 4; ch++) {
        const float* xb = Xs + (ch & 1) * 256 * XST;
#pragma unroll
        for (int kk = 0; kk < XCH; kk += 8) {
            unsigned af[2][4];
#pragma unroll
            for (int mt = 0; mt < 2; mt++) {
                int r = wr * 32 + mt * 16 + q;
                af[mt][0] = f2tf32(xb[r * XST + kk + t4]);
                af[mt][1] = f2tf32(xb[(r + 8) * XST + kk + t4]);
                af[mt][2] = f2tf32(xb[r * XST + kk + t4 + 4]);
                af[mt][3] = f2tf32(xb[(r + 8) * XST + kk + t4 + 4]);
            }
            int k0 = ch * XCH + kk;
            unsigned bf[8][2];
#pragma unroll
            for (int nt = 0; nt < 8; nt++) {
                int j = wc * 64 + nt * 8 + q;
                bf[nt][0] = Ws[j * WST + k0 + t4];
                bf[nt][1] = Ws[j * WST + k0 + t4 + 4];
            }
#pragma unroll
            for (int mt = 0; mt < 2; mt++)
#pragma unroll
                for (int nt = 0; nt < 8; nt++)
                    mma_tf32(acc[mt][nt], af[mt], bf[nt], acc[mt][nt]);
        }
        if (ch == 0) {
            __syncthreads();
            stage(2, 0);
            asm volatile("cp.async.wait_group 1;\n");
            __syncthreads();
        } else if (ch == 1) {
            __syncthreads();
            stage(3, 1);
            asm volatile("cp.async.wait_group 1;\n");
            __syncthreads();
        } else if (ch == 2) {
            __syncthreads();
            asm volatile("cp.async.wait_group 0;\n");
            __syncthreads();
        }
    }

#pragma unroll
    for (int mt = 0; mt < 2; mt++) {
#pragma unroll
        for (int half = 0; half < 2; half++) {
            int grow = row0 + wr * 32 + mt * 16 + q + half * 8;
            if (grow < N) {
#pragma unroll
                for (int nt = 0; nt < 8; nt++) {
                    int col = wc * 64 + nt * 8 + 2 * t4;
                    float2 v = make_float2(acc[mt][nt][2 * half],
                                           acc[mt][nt][2 * half + 1]);
                    *(float2*)&g_xw[(size_t)grow * GF + col] = v;
                }
            }
        }
    }
}

// ---------------------------------------------------------------------------
// Fused aggregate + bias + relu + linear + sigmoid.  One warp per node.
__global__ __launch_bounds__(256) void k_agg(const float* __restrict__ bconv,
                                             const float* __restrict__ wlin,
                                             const float* __restrict__ blin,
                                             float* __restrict__ h,
                                             float* __restrict__ out, int N) {
    int node = (blockIdx.x * blockDim.x + threadIdx.x) >> 5;
    int lane = threadIdx.x & 31;
    if (node >= N) return;

    const float* myrow = g_xw + (size_t)node * GF + lane * 4;
    float di = g_dinv[node];
    float self = di * di;
    float4 v = *(const float4*)myrow;
    float4 acc = make_float4(v.x * self, v.y * self, v.z * self, v.w * self);

    int p0 = g_start[node], p1 = g_start[node + 1];
    for (int p = p0; p < p1; p++) {
        int   s   = __ldg(&g_ssrc[p]);
        float nrm = __ldg(&g_snorm[p]);
        float4 m = *(const float4*)(g_xw + (size_t)s * GF + lane * 4);
        acc.x = fmaf(m.x, nrm, acc.x);
        acc.y = fmaf(m.y, nrm, acc.y);
        acc.z = fmaf(m.z, nrm, acc.z);
        acc.w = fmaf(m.w, nrm, acc.w);
    }

    float4 b = *(const float4*)(bconv + lane * 4);
    acc.x = fmaxf(acc.x + b.x, 0.0f);
    acc.y = fmaxf(acc.y + b.y, 0.0f);
    acc.z = fmaxf(acc.z + b.z, 0.0f);
    acc.w = fmaxf(acc.w + b.w, 0.0f);
    *(float4*)(h + (size_t)node * GF + lane * 4) = acc;

    float4 w = *(const float4*)(wlin + lane * 4);
    float dot = acc.x * w.x + acc.y * w.y + acc.z * w.z + acc.w * w.w;
#pragma unroll
    for (int o = 16; o; o >>= 1) dot += __shfl_xor_sync(0xFFFFFFFFu, dot, o);
    if (lane == 0) {
        float z = dot + blin[0];
        out[node] = 1.0f / (1.0f + expf(-z));
    }
}

// ---------------------------------------------------------------------------
extern "C" void kernel_launch(void* const* d_in, const int* in_sizes, int n_in,
                              void* d_out, int out_size) {
    const float* x  = (const float*)d_in[0];
    const int*   ei = (const int*)d_in[1];
    const float* Wc = (const float*)d_in[2];
    const float* bc = (const float*)d_in[3];
    const float* Wl = (const float*)d_in[4];
    const float* bl = (const float*)d_in[5];

    int N = in_sizes[0] / GF;
    int E = in_sizes[1] / 2;

    float* out = (float*)d_out;
    float* h   = out + N;
    const int* src = ei;
    const int* dst = ei + E;

    static bool inited = false;
    static cudaStream_t s2;
    static cudaEvent_t evFork, evJoin;
    const int smem_bytes = (2 * 256 * XST + 128 * WST) * 4;  // 141312
    if (!inited) {
        cudaFuncSetAttribute(k_gemm_tf32,
                             cudaFuncAttributeMaxDynamicSharedMemorySize,
                             smem_bytes);
        cudaStreamCreateWithFlags(&s2, cudaStreamNonBlocking);
        cudaEventCreateWithFlags(&evFork, cudaEventDisableTiming);
        cudaEventCreateWithFlags(&evJoin, cudaEventDisableTiming);
        inited = true;
    }

    // Fork: CSR build chain on side stream, GEMM on main stream (independent).
    cudaEventRecord(evFork, 0);
    cudaStreamWaitEvent(s2, evFork, 0);

    k_zero<<<(N + 255) / 256, 256, 0, s2>>>(N);
    k_cnt<<<(E + 255) / 256, 256, 0, s2>>>(dst, E);
    k_scan1<<<NPART, SCAN_BLK, 0, s2>>>(N);          // also computes dinv
    k_scan2<<<1, 128, 0, s2>>>();
    k_scan3<<<(N + 255) / 256, 256, 0, s2>>>(N, E);
    k_bin<<<(E + 255) / 256, 256, 0, s2>>>(src, dst, E);
    cudaEventRecord(evJoin, s2);

    // Main stream: GEMM runs concurrently with the CSR build.
    k_gemm_tf32<<<(N + 255) / 256, 512, smem_bytes>>>(x, Wc, N);

    // Join, then fused aggregate + epilogue (needs both).
    cudaStreamWaitEvent(0, evJoin, 0);
    k_agg<<<(N * 32 + 255) / 256, 256>>>(bc, Wl, bl, h, out, N);
}